// round 11
// baseline (speedup 1.0000x reference)
#include <cuda_runtime.h>
#include <cuda_fp16.h>
#include <cstdint>

#define N_NODES 50000
#define N_EDGES 640000
#define LDA 132                       // fp32 words per A row
#define LDB 136                       // fp32 words per B row (tf32 frag-major, pkern/nkern)
#define A_FLOATS (128 * LDA)          // 16896
#define B_FLOATS (128 * LDB)          // 17408
#define SMEM_BYTES ((A_FLOATS + 2 * B_FLOATS) * 4)  // 206848 (pkern/nkern)

// ---- ekern fp16 layout ----
#define LDAH 136                      // halves per fp16 A row (272B, LDSM conflict-free)
#define S_FLOATS (64 * LDA)           // 8448 floats = 33792 B staging per group
#define AH_HALVES (64 * LDAH)         // 8704 halves = 17408 B per group
#define BH_HALVES (128 * 128)         // 16384 halves = 32768 B per weight
#define EK_SMEM (2 * S_FLOATS * 4 + 2 * AH_HALVES * 2 + 2 * BH_HALVES * 2)  // 167936

// ---- scratch (__device__ globals; no allocations allowed) ----
__device__ float g_P[(size_t)N_NODES * 256];
__device__ float g_agg[(size_t)N_NODES * 128];
__device__ int   g_cnt[N_NODES];
__device__ int   g_row[N_EDGES];
__device__ int   g_col[N_EDGES];

// ---------------------------------------------------------------------------
// helpers
// ---------------------------------------------------------------------------
__device__ __forceinline__ uint32_t to_tf32(float x) {
    uint32_t r;
    asm("cvt.rna.tf32.f32 %0, %1;" : "=r"(r) : "f"(x));
    return r;
}
__device__ __forceinline__ uint32_t smem_u32(const void* p) {
    uint32_t a;
    asm("{ .reg .u64 t; cvta.to.shared.u64 t, %1; cvt.u32.u64 %0, t; }" : "=r"(a) : "l"(p));
    return a;
}
__device__ __forceinline__ void cp_async16(uint32_t saddr, const void* gsrc, int szbytes) {
    asm volatile("cp.async.ca.shared.global [%0], [%1], 16, %2;"
                 :: "r"(saddr), "l"(gsrc), "r"(szbytes) : "memory");
}
#define CP_COMMIT()   asm volatile("cp.async.commit_group;" ::: "memory")
#define CP_WAIT_ALL() asm volatile("cp.async.wait_group 0;" ::: "memory")
#define GBAR(id) asm volatile("bar.sync %0, 256;" :: "r"((id) + 1) : "memory")

// A tile (raw fp32 rows) via cp.async: 128 rows x 32 float4, 512 threads -> 8 each
__device__ __forceinline__ void cpa_tile(float* As, const float* __restrict__ X,
                                         int tid, int validRows) {
#pragma unroll
    for (int i = 0; i < 8; ++i) {
        int idx = tid + i * 512;
        int r = idx >> 5, c4 = (idx & 31) << 2;
        bool p = r < validRows;
        const float* src = X + (p ? ((size_t)r * 128 + c4) : 0);
        cp_async16(smem_u32(As + r * LDA + c4), src, p ? 16 : 0);
    }
}

// tf32 fragment-major B (pkern/nkern)
__device__ __forceinline__ void load_B_tf32(float* Bs, const float* __restrict__ W,
                                            int tid, int nthr) {
    for (int i = tid; i < 4096; i += nthr) {
        int k = i >> 5, n4 = (i & 31) << 2;
        float4 v = __ldg((const float4*)(W + k * 128 + n4));
        float vals[4] = {v.x, v.y, v.z, v.w};
#pragma unroll
        for (int j = 0; j < 4; ++j) {
            int n = n4 + j;
            int cp = (n & ~31) | ((n & 7) << 2) | ((n >> 3) & 3);
            *(uint32_t*)(Bs + k * LDB + cp) = to_tf32(vals[j]);
        }
    }
}

// fp16 fragment-major B for m16n8k16 (ekern): half index i encodes
// [ks(3)][wc(2)][lane(5)][ni(2)][q(2)]; per-lane 16 halves = 2x uint4
__device__ __forceinline__ void load_B_h16(__half* Bh, const float* __restrict__ W,
                                           int tid, int nthr) {
    for (int i = tid; i < BH_HALVES; i += nthr) {
        int l16 = i & 15, ni = l16 >> 2, q = l16 & 3;
        int lane = (i >> 4) & 31, g = lane >> 2, tig = lane & 3;
        int wcq = (i >> 9) & 3, ks = i >> 11;
        int k = ks * 16 + 2 * tig + (q & 1) + ((q >> 1) << 3);
        int n = wcq * 32 + ni * 8 + g;
        Bh[i] = __float2half(W[k * 128 + n]);
    }
}

// tf32 warp-tile GEMM (pkern/nkern, unchanged)
__device__ __forceinline__ void mma_tile32(const float* __restrict__ As,
                                           const float* __restrict__ Bs,
                                           float (&acc)[2][4][4],
                                           int lane, int warpM, int wc) {
    const int g = lane >> 2, tig = lane & 3;
#pragma unroll
    for (int ks = 0; ks < 16; ++ks) {
        const int k0 = ks * 8;
        uint32_t a[2][4];
#pragma unroll
        for (int mi = 0; mi < 2; ++mi) {
            const float* Ap = As + (warpM + mi * 16 + g) * LDA + k0 + tig;
            a[mi][0] = to_tf32(Ap[0]);
            a[mi][1] = to_tf32(Ap[8 * LDA]);
            a[mi][2] = to_tf32(Ap[4]);
            a[mi][3] = to_tf32(Ap[8 * LDA + 4]);
        }
        float4 b0 = *(const float4*)(Bs + (k0 + tig) * LDB + wc * 32 + (g << 2));
        float4 b1 = *(const float4*)(Bs + (k0 + tig + 4) * LDB + wc * 32 + (g << 2));
        uint32_t bA[4] = {__float_as_uint(b0.x), __float_as_uint(b0.y),
                          __float_as_uint(b0.z), __float_as_uint(b0.w)};
        uint32_t bB[4] = {__float_as_uint(b1.x), __float_as_uint(b1.y),
                          __float_as_uint(b1.z), __float_as_uint(b1.w)};
#pragma unroll
        for (int mi = 0; mi < 2; ++mi)
#pragma unroll
            for (int ni = 0; ni < 4; ++ni)
                asm volatile(
                    "mma.sync.aligned.m16n8k8.row.col.f32.tf32.tf32.f32 "
                    "{%0,%1,%2,%3}, {%4,%5,%6,%7}, {%8,%9}, {%0,%1,%2,%3};"
                    : "+f"(acc[mi][ni][0]), "+f"(acc[mi][ni][1]),
                      "+f"(acc[mi][ni][2]), "+f"(acc[mi][ni][3])
                    : "r"(a[mi][0]), "r"(a[mi][1]), "r"(a[mi][2]), "r"(a[mi][3]),
                      "r"(bA[ni]), "r"(bB[ni]));
    }
}

// fp16 warp-tile GEMM: 32 rows x 32 cols, K=128, ldmatrix A + frag-major B
__device__ __forceinline__ void mma_h16(const __half* __restrict__ A,
                                        const __half* __restrict__ Bh,
                                        float (&acc)[2][4][4],
                                        int lane, int warpM, int wc) {
    const int lrow = lane & 15, lk8 = (lane >> 4) << 3;
#pragma unroll
    for (int ks = 0; ks < 8; ++ks) {
        const int k0 = ks * 16;
        uint32_t a[2][4];
#pragma unroll
        for (int mi = 0; mi < 2; ++mi) {
            uint32_t ad = smem_u32(A + (warpM + mi * 16 + lrow) * LDAH + k0 + lk8);
            asm volatile("ldmatrix.sync.aligned.m8n8.x4.shared.b16 {%0,%1,%2,%3}, [%4];"
                         : "=r"(a[mi][0]), "=r"(a[mi][1]), "=r"(a[mi][2]), "=r"(a[mi][3])
                         : "r"(ad));
        }
        const uint4* bp = (const uint4*)(Bh + ((ks * 4 + wc) * 32 + lane) * 16);
        uint4 b01 = bp[0];
        uint4 b23 = bp[1];
        uint32_t bb[4][2] = {{b01.x, b01.y}, {b01.z, b01.w}, {b23.x, b23.y}, {b23.z, b23.w}};
#pragma unroll
        for (int mi = 0; mi < 2; ++mi)
#pragma unroll
            for (int ni = 0; ni < 4; ++ni)
                asm volatile(
                    "mma.sync.aligned.m16n8k16.row.col.f32.f16.f16.f32 "
                    "{%0,%1,%2,%3}, {%4,%5,%6,%7}, {%8,%9}, {%0,%1,%2,%3};"
                    : "+f"(acc[mi][ni][0]), "+f"(acc[mi][ni][1]),
                      "+f"(acc[mi][ni][2]), "+f"(acc[mi][ni][3])
                    : "r"(a[mi][0]), "r"(a[mi][1]), "r"(a[mi][2]), "r"(a[mi][3]),
                      "r"(bb[ni][0]), "r"(bb[ni][1]));
    }
}

__device__ __forceinline__ void zero_acc32(float (&acc)[2][4][4]) {
#pragma unroll
    for (int i = 0; i < 2; ++i)
#pragma unroll
        for (int j = 0; j < 4; ++j)
#pragma unroll
            for (int q = 0; q < 4; ++q) acc[i][j][q] = 0.f;
}

// ---------------------------------------------------------------------------
// setup kernels
// ---------------------------------------------------------------------------
__global__ void zero_kern() {
    int t = blockIdx.x * blockDim.x + threadIdx.x;
    int stride = gridDim.x * blockDim.x;
    float4* a4 = (float4*)g_agg;
    for (int i = t; i < N_NODES * 32; i += stride) a4[i] = make_float4(0.f, 0.f, 0.f, 0.f);
    for (int i = t; i < N_NODES; i += stride) g_cnt[i] = 0;
}

__global__ void conv_kern(const void* __restrict__ p) {
    const long long* q = (const long long*)p;
    int bad = 0;
    for (int i = threadIdx.x; i < 2048; i += blockDim.x) {
        long long v = q[i];
        if (v < 0 || v >= N_NODES) bad = 1;
    }
    int is32 = __syncthreads_or(bad);

    int t = blockIdx.x * blockDim.x + threadIdx.x;
    int stride = gridDim.x * blockDim.x;
    if (is32) {
        const int* qi = (const int*)p;
        for (int e = t; e < N_EDGES; e += stride) {
            int r = qi[e];
            g_row[e] = r;
            g_col[e] = qi[N_EDGES + e];
            atomicAdd(&g_cnt[r], 1);
        }
    } else {
        for (int e = t; e < N_EDGES; e += stride) {
            int r = (int)q[e];
            g_row[e] = r;
            g_col[e] = (int)q[N_EDGES + e];
            atomicAdd(&g_cnt[r], 1);
        }
    }
}

// ---------------------------------------------------------------------------
// pkern (tf32, unchanged from round 8)
// ---------------------------------------------------------------------------
__device__ __forceinline__ void mma_tile32_dual(const float* __restrict__ As,
                                                const float* __restrict__ B0s,
                                                const float* __restrict__ B1s,
                                                float (&acc1)[2][4][4], float (&acc2)[2][4][4],
                                                int lane, int warpM, int wc) {
    const int g = lane >> 2, tig = lane & 3;
#pragma unroll
    for (int ks = 0; ks < 16; ++ks) {
        const int k0 = ks * 8;
        uint32_t a[2][4];
#pragma unroll
        for (int mi = 0; mi < 2; ++mi) {
            const float* Ap = As + (warpM + mi * 16 + g) * LDA + k0 + tig;
            a[mi][0] = to_tf32(Ap[0]);
            a[mi][1] = to_tf32(Ap[8 * LDA]);
            a[mi][2] = to_tf32(Ap[4]);
            a[mi][3] = to_tf32(Ap[8 * LDA + 4]);
        }
#pragma unroll
        for (int which = 0; which < 2; ++which) {
            const float* Bs = which ? B1s : B0s;
            float4 b0 = *(const float4*)(Bs + (k0 + tig) * LDB + wc * 32 + (g << 2));
            float4 b1 = *(const float4*)(Bs + (k0 + tig + 4) * LDB + wc * 32 + (g << 2));
            uint32_t bA[4] = {__float_as_uint(b0.x), __float_as_uint(b0.y),
                              __float_as_uint(b0.z), __float_as_uint(b0.w)};
            uint32_t bB[4] = {__float_as_uint(b1.x), __float_as_uint(b1.y),
                              __float_as_uint(b1.z), __float_as_uint(b1.w)};
            float (&acc)[2][4][4] = which ? acc2 : acc1;
#pragma unroll
            for (int mi = 0; mi < 2; ++mi)
#pragma unroll
                for (int ni = 0; ni < 4; ++ni)
                    asm volatile(
                        "mma.sync.aligned.m16n8k8.row.col.f32.tf32.tf32.f32 "
                        "{%0,%1,%2,%3}, {%4,%5,%6,%7}, {%8,%9}, {%0,%1,%2,%3};"
                        : "+f"(acc[mi][ni][0]), "+f"(acc[mi][ni][1]),
                          "+f"(acc[mi][ni][2]), "+f"(acc[mi][ni][3])
                        : "r"(a[mi][0]), "r"(a[mi][1]), "r"(a[mi][2]), "r"(a[mi][3]),
                          "r"(bA[ni]), "r"(bB[ni]));
        }
    }
}

__global__ __launch_bounds__(512, 1) void pkern(const float* __restrict__ x,
                                                const float* __restrict__ We1) {
    extern __shared__ float sm[];
    float* A  = sm;
    float* B0 = sm + A_FLOATS;
    float* B1 = B0 + B_FLOATS;
    int tid = threadIdx.x, lane = tid & 31, wid = tid >> 5;
    int warpM = (wid >> 2) << 5, wc = wid & 3;
    int g = lane >> 2, tig = lane & 3;
    int nBase = blockIdx.x * 128;
    int valid = min(128, N_NODES - nBase);

    cpa_tile(A, x + (size_t)nBase * 128, tid, valid);
    CP_COMMIT();
    load_B_tf32(B0, We1, tid, 512);
    load_B_tf32(B1, We1 + 128 * 128, tid, 512);
    CP_WAIT_ALL();
    __syncthreads();

    float acc1[2][4][4], acc2[2][4][4];
    zero_acc32(acc1); zero_acc32(acc2);
    mma_tile32_dual(A, B0, B1, acc1, acc2, lane, warpM, wc);
    __syncthreads();

#pragma unroll
    for (int pass = 0; pass < 2; ++pass) {
        float (&acc)[2][4][4] = pass ? acc2 : acc1;
#pragma unroll
        for (int mi = 0; mi < 2; ++mi)
#pragma unroll
            for (int half = 0; half < 2; ++half) {
                int m = warpM + mi * 16 + g + half * 8;
#pragma unroll
                for (int ni = 0; ni < 4; ++ni) {
                    int c = wc * 32 + ni * 8 + 2 * tig;
                    *(float2*)(A + m * LDA + c) =
                        make_float2(acc[mi][ni][half * 2], acc[mi][ni][half * 2 + 1]);
                }
            }
        __syncthreads();
        int row = tid >> 2;
        int n = nBase + row;
        if (n < N_NODES) {
#pragma unroll
            for (int i = 0; i < 8; ++i) {
                int c = ((tid & 3) + i * 4) << 2;
                *(float4*)(g_P + (size_t)n * 256 + pass * 128 + c) = *(const float4*)(A + row * LDA + c);
            }
        }
        __syncthreads();
    }
}

// ---------------------------------------------------------------------------
// ekern v5: fp16 m16n8k16, two 8-warp groups, early S-prefetch, 2-pass output
// smem: [S0][S1] fp32 staging | [A0][A1] fp16 tiles | [B1h][B2h] frag-major fp16
// ---------------------------------------------------------------------------
__global__ __launch_bounds__(512, 1) void ekern(const float* __restrict__ attr,
                                                const float* __restrict__ We1,
                                                const float* __restrict__ be1,
                                                const float* __restrict__ We2,
                                                const float* __restrict__ be2,
                                                float* __restrict__ edge_out) {
    extern __shared__ float sm[];
    __half* Ah_base = (__half*)(sm + 2 * S_FLOATS);
    __half* B1h = Ah_base + 2 * AH_HALVES;
    __half* B2h = B1h + BH_HALVES;
    __shared__ int rows_s[2][2][64], cols_s[2][2][64];
    __shared__ float be1s[128], be2s[128];

    int tid = threadIdx.x, lane = tid & 31, wid = tid >> 5;
    int grp  = wid >> 3;
    int gtid = tid & 255;
    int gwid = wid & 7;
    int warpM = (gwid >> 2) << 5;
    int wc = gwid & 3;
    int g = lane >> 2, tig = lane & 3;
    const int cbase = wc * 32 + 2 * tig;
    float*  S  = sm + grp * S_FLOATS;
    __half* A  = Ah_base + grp * AH_HALVES;
    float*  A32 = (float*)A;             // 32-row fp32 output staging (17408B >= 32*132*4)

    load_B_h16(B1h, We1 + 2 * 128 * 128, tid, 512);  // W_e
    load_B_h16(B2h, We2, tid, 512);
    if (tid < 128) { be1s[tid] = be1[tid]; be2s[tid] = be2[tid]; }
    __syncthreads();

    const int NUM_T64 = N_EDGES / 64;     // 10000
    const int step = gridDim.x * 2;
    const int t0 = blockIdx.x * 2 + grp;

    // prologue: prefetch first tile into S
    {
        int eB = t0 << 6;
#pragma unroll
        for (int i = 0; i < 8; ++i) {
            int idx = gtid + i * 256;
            int r = idx >> 5, c4 = (idx & 31) << 2;
            cp_async16(smem_u32(S + r * LDA + c4), attr + (size_t)eB * 128 + r * 128 + c4, 16);
        }
        if (gtid < 16)
            cp_async16(smem_u32(&rows_s[grp][0][gtid * 4]), g_row + eB + gtid * 4, 16);
        else if (gtid < 32)
            cp_async16(smem_u32(&cols_s[grp][0][(gtid - 16) * 4]), g_col + eB + (gtid - 16) * 4, 16);
        CP_COMMIT();
    }

    int buf = 0;
    for (int t = t0; t < NUM_T64; t += step) {
        int eB = t << 6;
        CP_WAIT_ALL();
        GBAR(grp);   // S + indices visible

        // ---- convert S(fp32) -> A(fp16) ----
#pragma unroll
        for (int i = 0; i < 8; ++i) {
            int idx = gtid + i * 256;
            int r = idx >> 5, c4 = (idx & 31) << 2;
            float4 f = *(const float4*)(S + r * LDA + c4);
            union { __half2 h[2]; uint2 u; } cv;
            cv.h[0] = __floats2half2_rn(f.x, f.y);
            cv.h[1] = __floats2half2_rn(f.z, f.w);
            *(uint2*)(A + r * LDAH + c4) = cv.u;
        }
        GBAR(grp);   // A ready; S free

        // ---- early prefetch of next tile into S (overlaps both GEMMs) ----
        int tn = t + step;
        if (tn < NUM_T64) {
            int eN = tn << 6;
#pragma unroll
            for (int i = 0; i < 8; ++i) {
                int idx = gtid + i * 256;
                int r = idx >> 5, c4 = (idx & 31) << 2;
                cp_async16(smem_u32(S + r * LDA + c4), attr + (size_t)eN * 128 + r * 128 + c4, 16);
            }
            if (gtid < 16)
                cp_async16(smem_u32(&rows_s[grp][buf ^ 1][gtid * 4]), g_row + eN + gtid * 4, 16);
            else if (gtid < 32)
                cp_async16(smem_u32(&cols_s[grp][buf ^ 1][(gtid - 16) * 4]), g_col + eN + (gtid - 16) * 4, 16);
        }
        CP_COMMIT();

        // ---- P prefetch for mi=0 rows (hidden under GEMM1) ----
        int m0 = warpM + g, m1 = warpM + 8 + g;
        int r0 = rows_s[grp][buf][m0], c0i = cols_s[grp][buf][m0];
        int r1 = rows_s[grp][buf][m1], c1i = cols_s[grp][buf][m1];
        float2 ps0[2][4], pd0[2][4];
#pragma unroll
        for (int ni = 0; ni < 4; ++ni) {
            int c = cbase + ni * 8;
            ps0[0][ni] = *(const float2*)(g_P + (size_t)r0 * 256 + c);
            pd0[0][ni] = *(const float2*)(g_P + (size_t)c0i * 256 + 128 + c);
            ps0[1][ni] = *(const float2*)(g_P + (size_t)r1 * 256 + c);
            pd0[1][ni] = *(const float2*)(g_P + (size_t)c1i * 256 + 128 + c);
        }

        float acc1[2][4][4];
        zero_acc32(acc1);
        mma_h16(A, B1h, acc1, lane, warpM, wc);
        GBAR(grp);   // done reading A

        // ---- epilogue 1: h = relu(D1 + Psrc + Pdst + be1) -> A (fp16) ----
        {
            int m2 = warpM + 16 + g, m3 = warpM + 24 + g;
            int r2 = rows_s[grp][buf][m2], c2i = cols_s[grp][buf][m2];
            int r3 = rows_s[grp][buf][m3], c3i = cols_s[grp][buf][m3];
            float2 ps1[2][4], pd1[2][4];
#pragma unroll
            for (int ni = 0; ni < 4; ++ni) {
                int c = cbase + ni * 8;
                ps1[0][ni] = *(const float2*)(g_P + (size_t)r2 * 256 + c);
                pd1[0][ni] = *(const float2*)(g_P + (size_t)c2i * 256 + 128 + c);
                ps1[1][ni] = *(const float2*)(g_P + (size_t)r3 * 256 + c);
                pd1[1][ni] = *(const float2*)(g_P + (size_t)c3i * 256 + 128 + c);
            }
#pragma unroll
            for (int half = 0; half < 2; ++half) {
                int m = warpM + g + half * 8;
#pragma unroll
                for (int ni = 0; ni < 4; ++ni) {
                    int c = cbase + ni * 8;
                    float v0 = fmaxf(acc1[0][ni][half * 2]     + ps0[half][ni].x + pd0[half][ni].x + be1s[c],     0.f);
                    float v1 = fmaxf(acc1[0][ni][half * 2 + 1] + ps0[half][ni].y + pd0[half][ni].y + be1s[c + 1], 0.f);
                    *(__half2*)(A + m * LDAH + c) = __floats2half2_rn(v0, v1);
                }
            }
#pragma unroll
            for (int half = 0; half < 2; ++half) {
                int m = warpM + 16 + g + half * 8;
#pragma unroll
                for (int ni = 0; ni < 4; ++ni) {
                    int c = cbase + ni * 8;
                    float v0 = fmaxf(acc1[1][ni][half * 2]     + ps1[half][ni].x + pd1[half][ni].x + be1s[c],     0.f);
                    float v1 = fmaxf(acc1[1][ni][half * 2 + 1] + ps1[half][ni].y + pd1[half][ni].y + be1s[c + 1], 0.f);
                    *(__half2*)(A + m * LDAH + c) = __floats2half2_rn(v0, v1);
                }
            }
        }
        GBAR(grp);   // h visible

        float acc2[2][4][4];
        zero_acc32(acc2);
        mma_h16(A, B2h, acc2, lane, warpM, wc);
        GBAR(grp);   // done reading A(h)

        // ---- output: two 32-row passes staged through A32 ----
#pragma unroll
        for (int pass = 0; pass < 2; ++pass) {
            if ((warpM >> 5) == pass) {   // warps owning these rows stage
#pragma unroll
                for (int mi = 0; mi < 2; ++mi)
#pragma unroll
                    for (int half = 0; half < 2; ++half) {
                        int m = mi * 16 + half * 8 + g;   // 0..31 local
#pragma unroll
                        for (int ni = 0; ni < 4; ++ni) {
                            int c = cbase + ni * 8;
                            *(float2*)(A32 + m * LDA + c) =
                                make_float2(acc2[mi][ni][half * 2]     + be2s[c],
                                            acc2[mi][ni][half * 2 + 1] + be2s[c + 1]);
                        }
                    }
            }
            GBAR(grp);   // staged
            {
                int rr = gtid >> 3;                 // 0..31 local row
                int grow = pass * 32 + rr;
                int rdst = rows_s[grp][buf][grow];
                float* eo = edge_out + (size_t)(eB + grow) * 128;
                float* ag = g_agg + (size_t)rdst * 128;
#pragma unroll
                for (int i = 0; i < 4; ++i) {
                    int c = ((gtid & 7) + i * 8) << 2;
                    float4 v = *(const float4*)(A32 + rr * LDA + c);
                    *(float4*)(eo + c) = v;
                    atomicAdd((float4*)(ag + c), v);
                }
            }
            GBAR(grp);   // readers done -> A32 reusable / next iter convert safe
        }
        buf ^= 1;
    }
}

// ---------------------------------------------------------------------------
// nkern (tf32, unchanged from round 8)
// ---------------------------------------------------------------------------
__global__ __launch_bounds__(512, 1) void nkern(const float* __restrict__ x,
                                                const float* __restrict__ Wn1,
                                                const float* __restrict__ bn1,
                                                const float* __restrict__ Wn2,
                                                const float* __restrict__ bn2,
                                                float* __restrict__ x_out) {
    extern __shared__ float sm[];
    float* A  = sm;
    float* B0 = sm + A_FLOATS;
    float* B1 = B0 + B_FLOATS;
    __shared__ float bn1s[128], bn2s[128], scale_s[128];

    int tid = threadIdx.x, lane = tid & 31, wid = tid >> 5;
    int warpM = (wid >> 2) << 5, wc = wid & 3;
    int g = lane >> 2, tig = lane & 3;
    int nBase = blockIdx.x * 128;
    int valid = min(128, N_NODES - nBase);

    cpa_tile(A, x + (size_t)nBase * 128, tid, valid);
    CP_COMMIT();
    load_B_tf32(B0, Wn1, tid, 512);
    load_B_tf32(B1, Wn1 + 128 * 128, tid, 512);
    if (tid < 128) {
        bn1s[tid] = bn1[tid];
        bn2s[tid] = bn2[tid];
        int n = nBase + tid;
        float c = (n < N_NODES) ? (float)g_cnt[n] : 1.f;
        scale_s[tid] = 1.f / fmaxf(c, 1.f);
    }
    CP_WAIT_ALL();
    __syncthreads();

    float acc[2][4][4];
    zero_acc32(acc);
    mma_tile32(A, B0, acc, lane, warpM, wc);
    __syncthreads();

    for (int i = tid; i < 4096; i += 512) {
        int r = i >> 5, c4 = (i & 31) << 2;
        int n = nBase + r;
        float4 v = make_float4(0.f, 0.f, 0.f, 0.f);
        if (n < N_NODES) {
            v = *(const float4*)(g_agg + (size_t)n * 128 + c4);
            float s = scale_s[r];
            v.x *= s; v.y *= s; v.z *= s; v.w *= s;
        }
        *(float4*)(A + r * LDA + c4) = v;
    }
    __syncthreads();
    mma_tile32(A, B1, acc, lane, warpM, wc);
    __syncthreads();

#pragma unroll
    for (int mi = 0; mi < 2; ++mi)
#pragma unroll
        for (int half = 0; half < 2; ++half) {
            int m = warpM + mi * 16 + g + half * 8;
#pragma unroll
            for (int ni = 0; ni < 4; ++ni) {
                int c = wc * 32 + ni * 8 + 2 * tig;
                float v0 = fmaxf(acc[mi][ni][half * 2]     + bn1s[c],     0.f);
                float v1 = fmaxf(acc[mi][ni][half * 2 + 1] + bn1s[c + 1], 0.f);
                *(float2*)(A + m * LDA + c) = make_float2(v0, v1);
            }
        }
    load_B_tf32(B0, Wn2, tid, 512);
    __syncthreads();

    float acc2[2][4][4];
    zero_acc32(acc2);
    mma_tile32(A, B0, acc2, lane, warpM, wc);
    __syncthreads();

#pragma unroll
    for (int mi = 0; mi < 2; ++mi)
#pragma unroll
        for (int half = 0; half < 2; ++half) {
            int m = warpM + mi * 16 + g + half * 8;
#pragma unroll
            for (int ni = 0; ni < 4; ++ni) {
                int c = wc * 32 + ni * 8 + 2 * tig;
                *(float2*)(A + m * LDA + c) =
                    make_float2(acc2[mi][ni][half * 2]     + bn2s[c],
                                acc2[mi][ni][half * 2 + 1] + bn2s[c + 1]);
            }
        }
    __syncthreads();
    {
        int row = tid >> 2;
        int n = nBase + row;
        if (n < N_NODES) {
#pragma unroll
            for (int i = 0; i < 8; ++i) {
                int c = ((tid & 3) + i * 4) << 2;
                *(float4*)(x_out + (size_t)n * 128 + c) = *(const float4*)(A + row * LDA + c);
            }
        }
    }
}

// ---------------------------------------------------------------------------
extern "C" void kernel_launch(void* const* d_in, const int* in_sizes, int n_in,
                              void* d_out, int out_size) {
    const float* x    = (const float*)d_in[0];
    const void*  eidx = d_in[1];
    const float* attr = (const float*)d_in[2];
    const float* We1  = (const float*)d_in[3];
    const float* be1  = (const float*)d_in[4];
    const float* We2  = (const float*)d_in[5];
    const float* be2  = (const float*)d_in[6];
    const float* Wn1  = (const float*)d_in[7];
    const float* bn1  = (const float*)d_in[8];
    const float* Wn2  = (const float*)d_in[9];
    const float* bn2  = (const float*)d_in[10];

    float* out      = (float*)d_out;
    float* x_out    = out;                          // [N, 128]
    float* edge_out = out + (size_t)N_NODES * 128;  // [E, 128]

    cudaFuncSetAttribute(pkern, cudaFuncAttributeMaxDynamicSharedMemorySize, SMEM_BYTES);
    cudaFuncSetAttribute(ekern, cudaFuncAttributeMaxDynamicSharedMemorySize, EK_SMEM);
    cudaFuncSetAttribute(nkern, cudaFuncAttributeMaxDynamicSharedMemorySize, SMEM_BYTES);

    zero_kern<<<640, 256>>>();
    conv_kern<<<640, 256>>>(eidx);
    pkern<<<(N_NODES + 127) / 128, 512, SMEM_BYTES>>>(x, We1);
    ekern<<<148, 512, EK_SMEM>>>(attr, We1, be1, We2, be2, edge_out);
    nkern<<<(N_NODES + 127) / 128, 512, SMEM_BYTES>>>(x, Wn1, bn1, Wn2, bn2, x_out);
}

// round 12
// speedup vs baseline: 1.5048x; 1.5048x over previous
#include <cuda_runtime.h>
#include <cuda_fp16.h>
#include <cstdint>

#define N_NODES 50000
#define N_EDGES 640000
#define LDA 132                       // fp32 words per A row
#define LDB 136                       // fp32 words per B row (tf32 frag-major, pkern/nkern)
#define A_FLOATS (128 * LDA)          // 16896
#define B_FLOATS (128 * LDB)          // 17408
#define SMEM_BYTES ((A_FLOATS + 2 * B_FLOATS) * 4)  // 206848 (pkern/nkern)

// ---- ekern fp16 layout ----
#define LDAH 136                      // halves per fp16 A row (272B, LDSM conflict-free)
#define S_FLOATS (64 * LDA)           // 8448 floats = 33792 B staging per group
#define AH_HALVES (64 * LDAH)         // 8704 halves = 17408 B per group
#define BH_HALVES (128 * 128)         // 16384 halves = 32768 B per weight
#define EK_SMEM (2 * S_FLOATS * 4 + 2 * AH_HALVES * 2 + 2 * BH_HALVES * 2)  // 167936

// ---- scratch (__device__ globals; no allocations allowed) ----
__device__ float g_P[(size_t)N_NODES * 256];
__device__ float g_agg[(size_t)N_NODES * 128];
__device__ int   g_cnt[N_NODES];
__device__ int   g_row[N_EDGES];
__device__ int   g_col[N_EDGES];

// ---------------------------------------------------------------------------
// helpers
// ---------------------------------------------------------------------------
__device__ __forceinline__ uint32_t to_tf32(float x) {
    uint32_t r;
    asm("cvt.rna.tf32.f32 %0, %1;" : "=r"(r) : "f"(x));
    return r;
}
__device__ __forceinline__ uint32_t smem_u32(const void* p) {
    uint32_t a;
    asm("{ .reg .u64 t; cvta.to.shared.u64 t, %1; cvt.u32.u64 %0, t; }" : "=r"(a) : "l"(p));
    return a;
}
__device__ __forceinline__ void cp_async16(uint32_t saddr, const void* gsrc, int szbytes) {
    asm volatile("cp.async.ca.shared.global [%0], [%1], 16, %2;"
                 :: "r"(saddr), "l"(gsrc), "r"(szbytes) : "memory");
}
#define CP_COMMIT()   asm volatile("cp.async.commit_group;" ::: "memory")
#define CP_WAIT_ALL() asm volatile("cp.async.wait_group 0;" ::: "memory")
#define GBAR(id) asm volatile("bar.sync %0, 256;" :: "r"((id) + 1) : "memory")

// A tile (raw fp32 rows) via cp.async: 128 rows x 32 float4, 512 threads -> 8 each
__device__ __forceinline__ void cpa_tile(float* As, const float* __restrict__ X,
                                         int tid, int validRows) {
#pragma unroll
    for (int i = 0; i < 8; ++i) {
        int idx = tid + i * 512;
        int r = idx >> 5, c4 = (idx & 31) << 2;
        bool p = r < validRows;
        const float* src = X + (p ? ((size_t)r * 128 + c4) : 0);
        cp_async16(smem_u32(As + r * LDA + c4), src, p ? 16 : 0);
    }
}

// tf32 fragment-major B (pkern/nkern)
__device__ __forceinline__ void load_B_tf32(float* Bs, const float* __restrict__ W,
                                            int tid, int nthr) {
    for (int i = tid; i < 4096; i += nthr) {
        int k = i >> 5, n4 = (i & 31) << 2;
        float4 v = __ldg((const float4*)(W + k * 128 + n4));
        float vals[4] = {v.x, v.y, v.z, v.w};
#pragma unroll
        for (int j = 0; j < 4; ++j) {
            int n = n4 + j;
            int cp = (n & ~31) | ((n & 7) << 2) | ((n >> 3) & 3);
            *(uint32_t*)(Bs + k * LDB + cp) = to_tf32(vals[j]);
        }
    }
}

// fp16 B, DENSE-per-instruction layout:
// half index i = [ks(3)][wc(2)][j(1)][lane(5)][q8(3)]
// j selects which LDS.128 (ni pair {0,1} vs {2,3}); each 256-half block is
// 512B dense across lanes -> 4 wavefronts per LDS.128 (was 8 with per-lane-32B).
__device__ __forceinline__ void load_B_h16(__half* Bh, const float* __restrict__ W,
                                           int tid, int nthr) {
    for (int i = tid; i < BH_HALVES; i += nthr) {
        int q8 = i & 7, nil = q8 >> 2, q = q8 & 3;
        int lane = (i >> 3) & 31, g = lane >> 2, tig = lane & 3;
        int j = (i >> 8) & 1;
        int wcq = (i >> 9) & 3, ks = i >> 11;
        int ni = j * 2 + nil;
        int k = ks * 16 + 2 * tig + (q & 1) + ((q >> 1) << 3);
        int n = wcq * 32 + ni * 8 + g;
        Bh[i] = __float2half(W[k * 128 + n]);
    }
}

// tf32 warp-tile GEMM (pkern/nkern, unchanged)
__device__ __forceinline__ void mma_tile32(const float* __restrict__ As,
                                           const float* __restrict__ Bs,
                                           float (&acc)[2][4][4],
                                           int lane, int warpM, int wc) {
    const int g = lane >> 2, tig = lane & 3;
#pragma unroll
    for (int ks = 0; ks < 16; ++ks) {
        const int k0 = ks * 8;
        uint32_t a[2][4];
#pragma unroll
        for (int mi = 0; mi < 2; ++mi) {
            const float* Ap = As + (warpM + mi * 16 + g) * LDA + k0 + tig;
            a[mi][0] = to_tf32(Ap[0]);
            a[mi][1] = to_tf32(Ap[8 * LDA]);
            a[mi][2] = to_tf32(Ap[4]);
            a[mi][3] = to_tf32(Ap[8 * LDA + 4]);
        }
        float4 b0 = *(const float4*)(Bs + (k0 + tig) * LDB + wc * 32 + (g << 2));
        float4 b1 = *(const float4*)(Bs + (k0 + tig + 4) * LDB + wc * 32 + (g << 2));
        uint32_t bA[4] = {__float_as_uint(b0.x), __float_as_uint(b0.y),
                          __float_as_uint(b0.z), __float_as_uint(b0.w)};
        uint32_t bB[4] = {__float_as_uint(b1.x), __float_as_uint(b1.y),
                          __float_as_uint(b1.z), __float_as_uint(b1.w)};
#pragma unroll
        for (int mi = 0; mi < 2; ++mi)
#pragma unroll
            for (int ni = 0; ni < 4; ++ni)
                asm volatile(
                    "mma.sync.aligned.m16n8k8.row.col.f32.tf32.tf32.f32 "
                    "{%0,%1,%2,%3}, {%4,%5,%6,%7}, {%8,%9}, {%0,%1,%2,%3};"
                    : "+f"(acc[mi][ni][0]), "+f"(acc[mi][ni][1]),
                      "+f"(acc[mi][ni][2]), "+f"(acc[mi][ni][3])
                    : "r"(a[mi][0]), "r"(a[mi][1]), "r"(a[mi][2]), "r"(a[mi][3]),
                      "r"(bA[ni]), "r"(bB[ni]));
    }
}

// fp16 warp-tile GEMM: 32 rows x 32 cols, K=128, ldmatrix A + dense frag B
__device__ __forceinline__ void mma_h16(const __half* __restrict__ A,
                                        const __half* __restrict__ Bh,
                                        float (&acc)[2][4][4],
                                        int lane, int warpM, int wc) {
    const int lrow = lane & 15, lk8 = (lane >> 4) << 3;
#pragma unroll
    for (int ks = 0; ks < 8; ++ks) {
        const int k0 = ks * 16;
        uint32_t a[2][4];
#pragma unroll
        for (int mi = 0; mi < 2; ++mi) {
            uint32_t ad = smem_u32(A + (warpM + mi * 16 + lrow) * LDAH + k0 + lk8);
            asm volatile("ldmatrix.sync.aligned.m8n8.x4.shared.b16 {%0,%1,%2,%3}, [%4];"
                         : "=r"(a[mi][0]), "=r"(a[mi][1]), "=r"(a[mi][2]), "=r"(a[mi][3])
                         : "r"(ad));
        }
        const __half* bbase = Bh + (size_t)((ks * 4 + wc) * 2) * 256;
        uint4 b01 = *(const uint4*)(bbase + lane * 8);
        uint4 b23 = *(const uint4*)(bbase + 256 + lane * 8);
        uint32_t bb[4][2] = {{b01.x, b01.y}, {b01.z, b01.w}, {b23.x, b23.y}, {b23.z, b23.w}};
#pragma unroll
        for (int mi = 0; mi < 2; ++mi)
#pragma unroll
            for (int ni = 0; ni < 4; ++ni)
                asm volatile(
                    "mma.sync.aligned.m16n8k16.row.col.f32.f16.f16.f32 "
                    "{%0,%1,%2,%3}, {%4,%5,%6,%7}, {%8,%9}, {%0,%1,%2,%3};"
                    : "+f"(acc[mi][ni][0]), "+f"(acc[mi][ni][1]),
                      "+f"(acc[mi][ni][2]), "+f"(acc[mi][ni][3])
                    : "r"(a[mi][0]), "r"(a[mi][1]), "r"(a[mi][2]), "r"(a[mi][3]),
                      "r"(bb[ni][0]), "r"(bb[ni][1]));
    }
}

__device__ __forceinline__ void zero_acc32(float (&acc)[2][4][4]) {
#pragma unroll
    for (int i = 0; i < 2; ++i)
#pragma unroll
        for (int j = 0; j < 4; ++j)
#pragma unroll
            for (int q = 0; q < 4; ++q) acc[i][j][q] = 0.f;
}

// ---------------------------------------------------------------------------
// setup kernels
// ---------------------------------------------------------------------------
__global__ void zero_kern() {
    int t = blockIdx.x * blockDim.x + threadIdx.x;
    int stride = gridDim.x * blockDim.x;
    float4* a4 = (float4*)g_agg;
    for (int i = t; i < N_NODES * 32; i += stride) a4[i] = make_float4(0.f, 0.f, 0.f, 0.f);
    for (int i = t; i < N_NODES; i += stride) g_cnt[i] = 0;
}

__global__ void conv_kern(const void* __restrict__ p) {
    const long long* q = (const long long*)p;
    int bad = 0;
    for (int i = threadIdx.x; i < 2048; i += blockDim.x) {
        long long v = q[i];
        if (v < 0 || v >= N_NODES) bad = 1;
    }
    int is32 = __syncthreads_or(bad);

    int t = blockIdx.x * blockDim.x + threadIdx.x;
    int stride = gridDim.x * blockDim.x;
    if (is32) {
        const int* qi = (const int*)p;
        for (int e = t; e < N_EDGES; e += stride) {
            int r = qi[e];
            g_row[e] = r;
            g_col[e] = qi[N_EDGES + e];
            atomicAdd(&g_cnt[r], 1);
        }
    } else {
        for (int e = t; e < N_EDGES; e += stride) {
            int r = (int)q[e];
            g_row[e] = r;
            g_col[e] = (int)q[N_EDGES + e];
            atomicAdd(&g_cnt[r], 1);
        }
    }
}

// ---------------------------------------------------------------------------
// pkern (tf32, unchanged)
// ---------------------------------------------------------------------------
__device__ __forceinline__ void mma_tile32_dual(const float* __restrict__ As,
                                                const float* __restrict__ B0s,
                                                const float* __restrict__ B1s,
                                                float (&acc1)[2][4][4], float (&acc2)[2][4][4],
                                                int lane, int warpM, int wc) {
    const int g = lane >> 2, tig = lane & 3;
#pragma unroll
    for (int ks = 0; ks < 16; ++ks) {
        const int k0 = ks * 8;
        uint32_t a[2][4];
#pragma unroll
        for (int mi = 0; mi < 2; ++mi) {
            const float* Ap = As + (warpM + mi * 16 + g) * LDA + k0 + tig;
            a[mi][0] = to_tf32(Ap[0]);
            a[mi][1] = to_tf32(Ap[8 * LDA]);
            a[mi][2] = to_tf32(Ap[4]);
            a[mi][3] = to_tf32(Ap[8 * LDA + 4]);
        }
#pragma unroll
        for (int which = 0; which < 2; ++which) {
            const float* Bs = which ? B1s : B0s;
            float4 b0 = *(const float4*)(Bs + (k0 + tig) * LDB + wc * 32 + (g << 2));
            float4 b1 = *(const float4*)(Bs + (k0 + tig + 4) * LDB + wc * 32 + (g << 2));
            uint32_t bA[4] = {__float_as_uint(b0.x), __float_as_uint(b0.y),
                              __float_as_uint(b0.z), __float_as_uint(b0.w)};
            uint32_t bB[4] = {__float_as_uint(b1.x), __float_as_uint(b1.y),
                              __float_as_uint(b1.z), __float_as_uint(b1.w)};
            float (&acc)[2][4][4] = which ? acc2 : acc1;
#pragma unroll
            for (int mi = 0; mi < 2; ++mi)
#pragma unroll
                for (int ni = 0; ni < 4; ++ni)
                    asm volatile(
                        "mma.sync.aligned.m16n8k8.row.col.f32.tf32.tf32.f32 "
                        "{%0,%1,%2,%3}, {%4,%5,%6,%7}, {%8,%9}, {%0,%1,%2,%3};"
                        : "+f"(acc[mi][ni][0]), "+f"(acc[mi][ni][1]),
                          "+f"(acc[mi][ni][2]), "+f"(acc[mi][ni][3])
                        : "r"(a[mi][0]), "r"(a[mi][1]), "r"(a[mi][2]), "r"(a[mi][3]),
                          "r"(bA[ni]), "r"(bB[ni]));
        }
    }
}

__global__ __launch_bounds__(512, 1) void pkern(const float* __restrict__ x,
                                                const float* __restrict__ We1) {
    extern __shared__ float sm[];
    float* A  = sm;
    float* B0 = sm + A_FLOATS;
    float* B1 = B0 + B_FLOATS;
    int tid = threadIdx.x, lane = tid & 31, wid = tid >> 5;
    int warpM = (wid >> 2) << 5, wc = wid & 3;
    int g = lane >> 2, tig = lane & 3;
    int nBase = blockIdx.x * 128;
    int valid = min(128, N_NODES - nBase);

    cpa_tile(A, x + (size_t)nBase * 128, tid, valid);
    CP_COMMIT();
    load_B_tf32(B0, We1, tid, 512);
    load_B_tf32(B1, We1 + 128 * 128, tid, 512);
    CP_WAIT_ALL();
    __syncthreads();

    float acc1[2][4][4], acc2[2][4][4];
    zero_acc32(acc1); zero_acc32(acc2);
    mma_tile32_dual(A, B0, B1, acc1, acc2, lane, warpM, wc);
    __syncthreads();

#pragma unroll
    for (int pass = 0; pass < 2; ++pass) {
        float (&acc)[2][4][4] = pass ? acc2 : acc1;
#pragma unroll
        for (int mi = 0; mi < 2; ++mi)
#pragma unroll
            for (int half = 0; half < 2; ++half) {
                int m = warpM + mi * 16 + g + half * 8;
#pragma unroll
                for (int ni = 0; ni < 4; ++ni) {
                    int c = wc * 32 + ni * 8 + 2 * tig;
                    *(float2*)(A + m * LDA + c) =
                        make_float2(acc[mi][ni][half * 2], acc[mi][ni][half * 2 + 1]);
                }
            }
        __syncthreads();
        int row = tid >> 2;
        int n = nBase + row;
        if (n < N_NODES) {
#pragma unroll
            for (int i = 0; i < 8; ++i) {
                int c = ((tid & 3) + i * 4) << 2;
                *(float4*)(g_P + (size_t)n * 256 + pass * 128 + c) = *(const float4*)(A + row * LDA + c);
            }
        }
        __syncthreads();
    }
}

// ---------------------------------------------------------------------------
// ekern v6: fp16 m16n8k16, dense B fragments, two 8-warp groups,
// early S-prefetch, 2-pass output
// ---------------------------------------------------------------------------
__global__ __launch_bounds__(512, 1) void ekern(const float* __restrict__ attr,
                                                const float* __restrict__ We1,
                                                const float* __restrict__ be1,
                                                const float* __restrict__ We2,
                                                const float* __restrict__ be2,
                                                float* __restrict__ edge_out) {
    extern __shared__ float sm[];
    __half* Ah_base = (__half*)(sm + 2 * S_FLOATS);
    __half* B1h = Ah_base + 2 * AH_HALVES;
    __half* B2h = B1h + BH_HALVES;
    __shared__ int rows_s[2][2][64], cols_s[2][2][64];
    __shared__ float be1s[128], be2s[128];

    int tid = threadIdx.x, lane = tid & 31, wid = tid >> 5;
    int grp  = wid >> 3;
    int gtid = tid & 255;
    int gwid = wid & 7;
    int warpM = (gwid >> 2) << 5;
    int wc = gwid & 3;
    int g = lane >> 2, tig = lane & 3;
    const int cbase = wc * 32 + 2 * tig;
    float*  S  = sm + grp * S_FLOATS;
    __half* A  = Ah_base + grp * AH_HALVES;
    float*  A32 = (float*)A;             // 32-row fp32 output staging

    load_B_h16(B1h, We1 + 2 * 128 * 128, tid, 512);  // W_e
    load_B_h16(B2h, We2, tid, 512);
    if (tid < 128) { be1s[tid] = be1[tid]; be2s[tid] = be2[tid]; }
    __syncthreads();

    const int NUM_T64 = N_EDGES / 64;     // 10000
    const int step = gridDim.x * 2;
    const int t0 = blockIdx.x * 2 + grp;

    // prologue: prefetch first tile into S
    {
        int eB = t0 << 6;
#pragma unroll
        for (int i = 0; i < 8; ++i) {
            int idx = gtid + i * 256;
            int r = idx >> 5, c4 = (idx & 31) << 2;
            cp_async16(smem_u32(S + r * LDA + c4), attr + (size_t)eB * 128 + r * 128 + c4, 16);
        }
        if (gtid < 16)
            cp_async16(smem_u32(&rows_s[grp][0][gtid * 4]), g_row + eB + gtid * 4, 16);
        else if (gtid < 32)
            cp_async16(smem_u32(&cols_s[grp][0][(gtid - 16) * 4]), g_col + eB + (gtid - 16) * 4, 16);
        CP_COMMIT();
    }

    int buf = 0;
    for (int t = t0; t < NUM_T64; t += step) {
        int eB = t << 6;
        CP_WAIT_ALL();
        GBAR(grp);   // S + indices visible

        // ---- convert S(fp32) -> A(fp16) ----
#pragma unroll
        for (int i = 0; i < 8; ++i) {
            int idx = gtid + i * 256;
            int r = idx >> 5, c4 = (idx & 31) << 2;
            float4 f = *(const float4*)(S + r * LDA + c4);
            union { __half2 h[2]; uint2 u; } cv;
            cv.h[0] = __floats2half2_rn(f.x, f.y);
            cv.h[1] = __floats2half2_rn(f.z, f.w);
            *(uint2*)(A + r * LDAH + c4) = cv.u;
        }
        GBAR(grp);   // A ready; S free

        // ---- early prefetch of next tile into S (overlaps both GEMMs) ----
        int tn = t + step;
        if (tn < NUM_T64) {
            int eN = tn << 6;
#pragma unroll
            for (int i = 0; i < 8; ++i) {
                int idx = gtid + i * 256;
                int r = idx >> 5, c4 = (idx & 31) << 2;
                cp_async16(smem_u32(S + r * LDA + c4), attr + (size_t)eN * 128 + r * 128 + c4, 16);
            }
            if (gtid < 16)
                cp_async16(smem_u32(&rows_s[grp][buf ^ 1][gtid * 4]), g_row + eN + gtid * 4, 16);
            else if (gtid < 32)
                cp_async16(smem_u32(&cols_s[grp][buf ^ 1][(gtid - 16) * 4]), g_col + eN + (gtid - 16) * 4, 16);
        }
        CP_COMMIT();

        // ---- P prefetch for mi=0 rows (hidden under GEMM1) ----
        int m0 = warpM + g, m1 = warpM + 8 + g;
        int r0 = rows_s[grp][buf][m0], c0i = cols_s[grp][buf][m0];
        int r1 = rows_s[grp][buf][m1], c1i = cols_s[grp][buf][m1];
        float2 ps0[2][4], pd0[2][4];
#pragma unroll
        for (int ni = 0; ni < 4; ++ni) {
            int c = cbase + ni * 8;
            ps0[0][ni] = *(const float2*)(g_P + (size_t)r0 * 256 + c);
            pd0[0][ni] = *(const float2*)(g_P + (size_t)c0i * 256 + 128 + c);
            ps0[1][ni] = *(const float2*)(g_P + (size_t)r1 * 256 + c);
            pd0[1][ni] = *(const float2*)(g_P + (size_t)c1i * 256 + 128 + c);
        }

        float acc1[2][4][4];
        zero_acc32(acc1);
        mma_h16(A, B1h, acc1, lane, warpM, wc);
        GBAR(grp);   // done reading A

        // ---- epilogue 1: h = relu(D1 + Psrc + Pdst + be1) -> A (fp16) ----
        {
            int m2 = warpM + 16 + g, m3 = warpM + 24 + g;
            int r2 = rows_s[grp][buf][m2], c2i = cols_s[grp][buf][m2];
            int r3 = rows_s[grp][buf][m3], c3i = cols_s[grp][buf][m3];
            float2 ps1[2][4], pd1[2][4];
#pragma unroll
            for (int ni = 0; ni < 4; ++ni) {
                int c = cbase + ni * 8;
                ps1[0][ni] = *(const float2*)(g_P + (size_t)r2 * 256 + c);
                pd1[0][ni] = *(const float2*)(g_P + (size_t)c2i * 256 + 128 + c);
                ps1[1][ni] = *(const float2*)(g_P + (size_t)r3 * 256 + c);
                pd1[1][ni] = *(const float2*)(g_P + (size_t)c3i * 256 + 128 + c);
            }
#pragma unroll
            for (int half = 0; half < 2; ++half) {
                int m = warpM + g + half * 8;
#pragma unroll
                for (int ni = 0; ni < 4; ++ni) {
                    int c = cbase + ni * 8;
                    float v0 = fmaxf(acc1[0][ni][half * 2]     + ps0[half][ni].x + pd0[half][ni].x + be1s[c],     0.f);
                    float v1 = fmaxf(acc1[0][ni][half * 2 + 1] + ps0[half][ni].y + pd0[half][ni].y + be1s[c + 1], 0.f);
                    *(__half2*)(A + m * LDAH + c) = __floats2half2_rn(v0, v1);
                }
            }
#pragma unroll
            for (int half = 0; half < 2; ++half) {
                int m = warpM + 16 + g + half * 8;
#pragma unroll
                for (int ni = 0; ni < 4; ++ni) {
                    int c = cbase + ni * 8;
                    float v0 = fmaxf(acc1[1][ni][half * 2]     + ps1[half][ni].x + pd1[half][ni].x + be1s[c],     0.f);
                    float v1 = fmaxf(acc1[1][ni][half * 2 + 1] + ps1[half][ni].y + pd1[half][ni].y + be1s[c + 1], 0.f);
                    *(__half2*)(A + m * LDAH + c) = __floats2half2_rn(v0, v1);
                }
            }
        }
        GBAR(grp);   // h visible

        float acc2[2][4][4];
        zero_acc32(acc2);
        mma_h16(A, B2h, acc2, lane, warpM, wc);
        GBAR(grp);   // done reading A(h)

        // ---- output: two 32-row passes staged through A32 ----
#pragma unroll
        for (int pass = 0; pass < 2; ++pass) {
            if ((warpM >> 5) == pass) {
#pragma unroll
                for (int mi = 0; mi < 2; ++mi)
#pragma unroll
                    for (int half = 0; half < 2; ++half) {
                        int m = mi * 16 + half * 8 + g;
#pragma unroll
                        for (int ni = 0; ni < 4; ++ni) {
                            int c = cbase + ni * 8;
                            *(float2*)(A32 + m * LDA + c) =
                                make_float2(acc2[mi][ni][half * 2]     + be2s[c],
                                            acc2[mi][ni][half * 2 + 1] + be2s[c + 1]);
                        }
                    }
            }
            GBAR(grp);   // staged
            {
                int rr = gtid >> 3;
                int grow = pass * 32 + rr;
                int rdst = rows_s[grp][buf][grow];
                float* eo = edge_out + (size_t)(eB + grow) * 128;
                float* ag = g_agg + (size_t)rdst * 128;
#pragma unroll
                for (int i = 0; i < 4; ++i) {
                    int c = ((gtid & 7) + i * 8) << 2;
                    float4 v = *(const float4*)(A32 + rr * LDA + c);
                    *(float4*)(eo + c) = v;
                    atomicAdd((float4*)(ag + c), v);
                }
            }
            GBAR(grp);   // readers done
        }
        buf ^= 1;
    }
}

// ---------------------------------------------------------------------------
// nkern (tf32, unchanged)
// ---------------------------------------------------------------------------
__global__ __launch_bounds__(512, 1) void nkern(const float* __restrict__ x,
                                                const float* __restrict__ Wn1,
                                                const float* __restrict__ bn1,
                                                const float* __restrict__ Wn2,
                                                const float* __restrict__ bn2,
                                                float* __restrict__ x_out) {
    extern __shared__ float sm[];
    float* A  = sm;
    float* B0 = sm + A_FLOATS;
    float* B1 = B0 + B_FLOATS;
    __shared__ float bn1s[128], bn2s[128], scale_s[128];

    int tid = threadIdx.x, lane = tid & 31, wid = tid >> 5;
    int warpM = (wid >> 2) << 5, wc = wid & 3;
    int g = lane >> 2, tig = lane & 3;
    int nBase = blockIdx.x * 128;
    int valid = min(128, N_NODES - nBase);

    cpa_tile(A, x + (size_t)nBase * 128, tid, valid);
    CP_COMMIT();
    load_B_tf32(B0, Wn1, tid, 512);
    load_B_tf32(B1, Wn1 + 128 * 128, tid, 512);
    if (tid < 128) {
        bn1s[tid] = bn1[tid];
        bn2s[tid] = bn2[tid];
        int n = nBase + tid;
        float c = (n < N_NODES) ? (float)g_cnt[n] : 1.f;
        scale_s[tid] = 1.f / fmaxf(c, 1.f);
    }
    CP_WAIT_ALL();
    __syncthreads();

    float acc[2][4][4];
    zero_acc32(acc);
    mma_tile32(A, B0, acc, lane, warpM, wc);
    __syncthreads();

    for (int i = tid; i < 4096; i += 512) {
        int r = i >> 5, c4 = (i & 31) << 2;
        int n = nBase + r;
        float4 v = make_float4(0.f, 0.f, 0.f, 0.f);
        if (n < N_NODES) {
            v = *(const float4*)(g_agg + (size_t)n * 128 + c4);
            float s = scale_s[r];
            v.x *= s; v.y *= s; v.z *= s; v.w *= s;
        }
        *(float4*)(A + r * LDA + c4) = v;
    }
    __syncthreads();
    mma_tile32(A, B1, acc, lane, warpM, wc);
    __syncthreads();

#pragma unroll
    for (int mi = 0; mi < 2; ++mi)
#pragma unroll
        for (int half = 0; half < 2; ++half) {
            int m = warpM + mi * 16 + g + half * 8;
#pragma unroll
            for (int ni = 0; ni < 4; ++ni) {
                int c = wc * 32 + ni * 8 + 2 * tig;
                float v0 = fmaxf(acc[mi][ni][half * 2]     + bn1s[c],     0.f);
                float v1 = fmaxf(acc[mi][ni][half * 2 + 1] + bn1s[c + 1], 0.f);
                *(float2*)(A + m * LDA + c) = make_float2(v0, v1);
            }
        }
    load_B_tf32(B0, Wn2, tid, 512);
    __syncthreads();

    float acc2[2][4][4];
    zero_acc32(acc2);
    mma_tile32(A, B0, acc2, lane, warpM, wc);
    __syncthreads();

#pragma unroll
    for (int mi = 0; mi < 2; ++mi)
#pragma unroll
        for (int half = 0; half < 2; ++half) {
            int m = warpM + mi * 16 + g + half * 8;
#pragma unroll
            for (int ni = 0; ni < 4; ++ni) {
                int c = wc * 32 + ni * 8 + 2 * tig;
                *(float2*)(A + m * LDA + c) =
                    make_float2(acc2[mi][ni][half * 2]     + bn2s[c],
                                acc2[mi][ni][half * 2 + 1] + bn2s[c + 1]);
            }
        }
    __syncthreads();
    {
        int row = tid >> 2;
        int n = nBase + row;
        if (n < N_NODES) {
#pragma unroll
            for (int i = 0; i < 8; ++i) {
                int c = ((tid & 3) + i * 4) << 2;
                *(float4*)(x_out + (size_t)n * 128 + c) = *(const float4*)(A + row * LDA + c);
            }
        }
    }
}

// ---------------------------------------------------------------------------
extern "C" void kernel_launch(void* const* d_in, const int* in_sizes, int n_in,
                              void* d_out, int out_size) {
    const float* x    = (const float*)d_in[0];
    const void*  eidx = d_in[1];
    const float* attr = (const float*)d_in[2];
    const float* We1  = (const float*)d_in[3];
    const float* be1  = (const float*)d_in[4];
    const float* We2  = (const float*)d_in[5];
    const float* be2  = (const float*)d_in[6];
    const float* Wn1  = (const float*)d_in[7];
    const float* bn1  = (const float*)d_in[8];
    const float* Wn2  = (const float*)d_in[9];
    const float* bn2  = (const float*)d_in[10];

    float* out      = (float*)d_out;
    float* x_out    = out;                          // [N, 128]
    float* edge_out = out + (size_t)N_NODES * 128;  // [E, 128]

    cudaFuncSetAttribute(pkern, cudaFuncAttributeMaxDynamicSharedMemorySize, SMEM_BYTES);
    cudaFuncSetAttribute(ekern, cudaFuncAttributeMaxDynamicSharedMemorySize, EK_SMEM);
    cudaFuncSetAttribute(nkern, cudaFuncAttributeMaxDynamicSharedMemorySize, SMEM_BYTES);

    zero_kern<<<640, 256>>>();
    conv_kern<<<640, 256>>>(eidx);
    pkern<<<(N_NODES + 127) / 128, 512, SMEM_BYTES>>>(x, We1);
    ekern<<<148, 512, EK_SMEM>>>(attr, We1, be1, We2, be2, edge_out);
    nkern<<<(N_NODES + 127) / 128, 512, SMEM_BYTES>>>(x, Wn1, bn1, Wn2, bn2, x_out);
}

// round 15
// speedup vs baseline: 1.6848x; 1.1197x over previous
#include <cuda_runtime.h>
#include <cuda_fp16.h>
#include <cstdint>

#define N_NODES 50000
#define N_EDGES 640000
#define LDA 132                       // fp32 words per A row
#define LDB 136                       // fp32 words per B row (tf32 frag-major, pkern/nkern)
#define A_FLOATS (128 * LDA)          // 16896
#define B_FLOATS (128 * LDB)          // 17408
#define SMEM_BYTES ((A_FLOATS + 2 * B_FLOATS) * 4)  // 206848 (pkern/nkern)

// ---- ekern fp16 layout ----
#define LDAH 136                      // halves per fp16 A row (272B, LDSM conflict-free)
#define S_FLOATS (64 * LDA)           // 8448 floats staging per group
#define AH_HALVES (64 * LDAH)         // 8704 halves per group
#define BH_HALVES (128 * 128)         // 16384 halves per weight
#define EK_SMEM (2 * S_FLOATS * 4 + 2 * AH_HALVES * 2 + 2 * BH_HALVES * 2)  // 167936

// ---- scratch (__device__ globals; no allocations allowed) ----
// g_P_h: fp16, fragment-permuted. node*256 + side*128 + wc*32 + tig*8 + ni*2 + q
// where original col c = wc*32 + ni*8 + 2*tig + q.  side 0 = x@W_src, 1 = x@W_dst.
// __align__(16): uint4 ld/st target — wide-op alignment is a hard HW requirement.
__device__ __align__(16) __half g_P_h[(size_t)N_NODES * 256];
__device__ float g_agg[(size_t)N_NODES * 128];
__device__ int   g_cnt[N_NODES];
__device__ int   g_row[N_EDGES];
__device__ int   g_col[N_EDGES];

// ---------------------------------------------------------------------------
// helpers
// ---------------------------------------------------------------------------
__device__ __forceinline__ uint32_t to_tf32(float x) {
    uint32_t r;
    asm("cvt.rna.tf32.f32 %0, %1;" : "=r"(r) : "f"(x));
    return r;
}
__device__ __forceinline__ uint32_t smem_u32(const void* p) {
    uint32_t a;
    asm("{ .reg .u64 t; cvta.to.shared.u64 t, %1; cvt.u32.u64 %0, t; }" : "=r"(a) : "l"(p));
    return a;
}
__device__ __forceinline__ void cp_async16(uint32_t saddr, const void* gsrc, int szbytes) {
    asm volatile("cp.async.ca.shared.global [%0], [%1], 16, %2;"
                 :: "r"(saddr), "l"(gsrc), "r"(szbytes) : "memory");
}
#define CP_COMMIT()   asm volatile("cp.async.commit_group;" ::: "memory")
#define CP_WAIT_ALL() asm volatile("cp.async.wait_group 0;" ::: "memory")
#define GBAR(id) asm volatile("bar.sync %0, 256;" :: "r"((id) + 1) : "memory")

// A tile (raw fp32 rows) via cp.async: 128 rows x 32 float4, 512 threads -> 8 each
__device__ __forceinline__ void cpa_tile(float* As, const float* __restrict__ X,
                                         int tid, int validRows) {
#pragma unroll
    for (int i = 0; i < 8; ++i) {
        int idx = tid + i * 512;
        int r = idx >> 5, c4 = (idx & 31) << 2;
        bool p = r < validRows;
        const float* src = X + (p ? ((size_t)r * 128 + c4) : 0);
        cp_async16(smem_u32(As + r * LDA + c4), src, p ? 16 : 0);
    }
}

// tf32 fragment-major B (pkern/nkern)
__device__ __forceinline__ void load_B_tf32(float* Bs, const float* __restrict__ W,
                                            int tid, int nthr) {
    for (int i = tid; i < 4096; i += nthr) {
        int k = i >> 5, n4 = (i & 31) << 2;
        float4 v = __ldg((const float4*)(W + k * 128 + n4));
        float vals[4] = {v.x, v.y, v.z, v.w};
#pragma unroll
        for (int j = 0; j < 4; ++j) {
            int n = n4 + j;
            int cp = (n & ~31) | ((n & 7) << 2) | ((n >> 3) & 3);
            *(uint32_t*)(Bs + k * LDB + cp) = to_tf32(vals[j]);
        }
    }
}

// fp16 B, DENSE-per-instruction layout (validated round 12):
// half index i = [ks(3)][wc(2)][j(1)][lane(5)][q8(3)]
__device__ __forceinline__ void load_B_h16(__half* Bh, const float* __restrict__ W,
                                           int tid, int nthr) {
    for (int i = tid; i < BH_HALVES; i += nthr) {
        int q8 = i & 7, nil = q8 >> 2, q = q8 & 3;
        int lane = (i >> 3) & 31, g = lane >> 2, tig = lane & 3;
        int j = (i >> 8) & 1;
        int wcq = (i >> 9) & 3, ks = i >> 11;
        int ni = j * 2 + nil;
        int k = ks * 16 + 2 * tig + (q & 1) + ((q >> 1) << 3);
        int n = wcq * 32 + ni * 8 + g;
        Bh[i] = __float2half(W[k * 128 + n]);
    }
}

// tf32 warp-tile GEMM (nkern)
__device__ __forceinline__ void mma_tile32(const float* __restrict__ As,
                                           const float* __restrict__ Bs,
                                           float (&acc)[2][4][4],
                                           int lane, int warpM, int wc) {
    const int g = lane >> 2, tig = lane & 3;
#pragma unroll
    for (int ks = 0; ks < 16; ++ks) {
        const int k0 = ks * 8;
        uint32_t a[2][4];
#pragma unroll
        for (int mi = 0; mi < 2; ++mi) {
            const float* Ap = As + (warpM + mi * 16 + g) * LDA + k0 + tig;
            a[mi][0] = to_tf32(Ap[0]);
            a[mi][1] = to_tf32(Ap[8 * LDA]);
            a[mi][2] = to_tf32(Ap[4]);
            a[mi][3] = to_tf32(Ap[8 * LDA + 4]);
        }
        float4 b0 = *(const float4*)(Bs + (k0 + tig) * LDB + wc * 32 + (g << 2));
        float4 b1 = *(const float4*)(Bs + (k0 + tig + 4) * LDB + wc * 32 + (g << 2));
        uint32_t bA[4] = {__float_as_uint(b0.x), __float_as_uint(b0.y),
                          __float_as_uint(b0.z), __float_as_uint(b0.w)};
        uint32_t bB[4] = {__float_as_uint(b1.x), __float_as_uint(b1.y),
                          __float_as_uint(b1.z), __float_as_uint(b1.w)};
#pragma unroll
        for (int mi = 0; mi < 2; ++mi)
#pragma unroll
            for (int ni = 0; ni < 4; ++ni)
                asm volatile(
                    "mma.sync.aligned.m16n8k8.row.col.f32.tf32.tf32.f32 "
                    "{%0,%1,%2,%3}, {%4,%5,%6,%7}, {%8,%9}, {%0,%1,%2,%3};"
                    : "+f"(acc[mi][ni][0]), "+f"(acc[mi][ni][1]),
                      "+f"(acc[mi][ni][2]), "+f"(acc[mi][ni][3])
                    : "r"(a[mi][0]), "r"(a[mi][1]), "r"(a[mi][2]), "r"(a[mi][3]),
                      "r"(bA[ni]), "r"(bB[ni]));
    }
}

// fp16 warp-tile GEMM: 32 rows x 32 cols, K=128, ldmatrix A + dense frag B
__device__ __forceinline__ void mma_h16(const __half* __restrict__ A,
                                        const __half* __restrict__ Bh,
                                        float (&acc)[2][4][4],
                                        int lane, int warpM, int wc) {
    const int lrow = lane & 15, lk8 = (lane >> 4) << 3;
#pragma unroll
    for (int ks = 0; ks < 8; ++ks) {
        const int k0 = ks * 16;
        uint32_t a[2][4];
#pragma unroll
        for (int mi = 0; mi < 2; ++mi) {
            uint32_t ad = smem_u32(A + (warpM + mi * 16 + lrow) * LDAH + k0 + lk8);
            asm volatile("ldmatrix.sync.aligned.m8n8.x4.shared.b16 {%0,%1,%2,%3}, [%4];"
                         : "=r"(a[mi][0]), "=r"(a[mi][1]), "=r"(a[mi][2]), "=r"(a[mi][3])
                         : "r"(ad));
        }
        const __half* bbase = Bh + (size_t)((ks * 4 + wc) * 2) * 256;
        uint4 b01 = *(const uint4*)(bbase + lane * 8);
        uint4 b23 = *(const uint4*)(bbase + 256 + lane * 8);
        uint32_t bb[4][2] = {{b01.x, b01.y}, {b01.z, b01.w}, {b23.x, b23.y}, {b23.z, b23.w}};
#pragma unroll
        for (int mi = 0; mi < 2; ++mi)
#pragma unroll
            for (int ni = 0; ni < 4; ++ni)
                asm volatile(
                    "mma.sync.aligned.m16n8k16.row.col.f32.f16.f16.f32 "
                    "{%0,%1,%2,%3}, {%4,%5,%6,%7}, {%8,%9}, {%0,%1,%2,%3};"
                    : "+f"(acc[mi][ni][0]), "+f"(acc[mi][ni][1]),
                      "+f"(acc[mi][ni][2]), "+f"(acc[mi][ni][3])
                    : "r"(a[mi][0]), "r"(a[mi][1]), "r"(a[mi][2]), "r"(a[mi][3]),
                      "r"(bb[ni][0]), "r"(bb[ni][1]));
    }
}

__device__ __forceinline__ void zero_acc32(float (&acc)[2][4][4]) {
#pragma unroll
    for (int i = 0; i < 2; ++i)
#pragma unroll
        for (int j = 0; j < 4; ++j)
#pragma unroll
            for (int q = 0; q < 4; ++q) acc[i][j][q] = 0.f;
}

// ---------------------------------------------------------------------------
// setup kernels
// ---------------------------------------------------------------------------
__global__ void zero_kern() {
    int t = blockIdx.x * blockDim.x + threadIdx.x;
    int stride = gridDim.x * blockDim.x;
    float4* a4 = (float4*)g_agg;
    for (int i = t; i < N_NODES * 32; i += stride) a4[i] = make_float4(0.f, 0.f, 0.f, 0.f);
    for (int i = t; i < N_NODES; i += stride) g_cnt[i] = 0;
}

__global__ void conv_kern(const void* __restrict__ p) {
    const long long* q = (const long long*)p;
    int bad = 0;
    for (int i = threadIdx.x; i < 2048; i += blockDim.x) {
        long long v = q[i];
        if (v < 0 || v >= N_NODES) bad = 1;
    }
    int is32 = __syncthreads_or(bad);

    int t = blockIdx.x * blockDim.x + threadIdx.x;
    int stride = gridDim.x * blockDim.x;
    if (is32) {
        const int* qi = (const int*)p;
        for (int e = t; e < N_EDGES; e += stride) {
            int r = qi[e];
            g_row[e] = r;
            g_col[e] = qi[N_EDGES + e];
            atomicAdd(&g_cnt[r], 1);
        }
    } else {
        for (int e = t; e < N_EDGES; e += stride) {
            int r = (int)q[e];
            g_row[e] = r;
            g_col[e] = (int)q[N_EDGES + e];
            atomicAdd(&g_cnt[r], 1);
        }
    }
}

// ---------------------------------------------------------------------------
// pkern: g_P_h = fp16-permuted( x @ [W_src | W_dst] )   (tf32 dual-B MMA,
// DIRECT register->gmem fp16 stores; no smem staging epilogue)
// ---------------------------------------------------------------------------
__device__ __forceinline__ void mma_tile32_dual(const float* __restrict__ As,
                                                const float* __restrict__ B0s,
                                                const float* __restrict__ B1s,
                                                float (&acc1)[2][4][4], float (&acc2)[2][4][4],
                                                int lane, int warpM, int wc) {
    const int g = lane >> 2, tig = lane & 3;
#pragma unroll
    for (int ks = 0; ks < 16; ++ks) {
        const int k0 = ks * 8;
        uint32_t a[2][4];
#pragma unroll
        for (int mi = 0; mi < 2; ++mi) {
            const float* Ap = As + (warpM + mi * 16 + g) * LDA + k0 + tig;
            a[mi][0] = to_tf32(Ap[0]);
            a[mi][1] = to_tf32(Ap[8 * LDA]);
            a[mi][2] = to_tf32(Ap[4]);
            a[mi][3] = to_tf32(Ap[8 * LDA + 4]);
        }
#pragma unroll
        for (int which = 0; which < 2; ++which) {
            const float* Bs = which ? B1s : B0s;
            float4 b0 = *(const float4*)(Bs + (k0 + tig) * LDB + wc * 32 + (g << 2));
            float4 b1 = *(const float4*)(Bs + (k0 + tig + 4) * LDB + wc * 32 + (g << 2));
            uint32_t bA[4] = {__float_as_uint(b0.x), __float_as_uint(b0.y),
                              __float_as_uint(b0.z), __float_as_uint(b0.w)};
            uint32_t bB[4] = {__float_as_uint(b1.x), __float_as_uint(b1.y),
                              __float_as_uint(b1.z), __float_as_uint(b1.w)};
            float (&acc)[2][4][4] = which ? acc2 : acc1;
#pragma unroll
            for (int mi = 0; mi < 2; ++mi)
#pragma unroll
                for (int ni = 0; ni < 4; ++ni)
                    asm volatile(
                        "mma.sync.aligned.m16n8k8.row.col.f32.tf32.tf32.f32 "
                        "{%0,%1,%2,%3}, {%4,%5,%6,%7}, {%8,%9}, {%0,%1,%2,%3};"
                        : "+f"(acc[mi][ni][0]), "+f"(acc[mi][ni][1]),
                          "+f"(acc[mi][ni][2]), "+f"(acc[mi][ni][3])
                        : "r"(a[mi][0]), "r"(a[mi][1]), "r"(a[mi][2]), "r"(a[mi][3]),
                          "r"(bA[ni]), "r"(bB[ni]));
        }
    }
}

__global__ __launch_bounds__(512, 1) void pkern(const float* __restrict__ x,
                                                const float* __restrict__ We1) {
    extern __shared__ float sm[];
    float* A  = sm;
    float* B0 = sm + A_FLOATS;
    float* B1 = B0 + B_FLOATS;
    int tid = threadIdx.x, lane = tid & 31, wid = tid >> 5;
    int warpM = (wid >> 2) << 5, wc = wid & 3;
    int g = lane >> 2, tig = lane & 3;
    int nBase = blockIdx.x * 128;
    int valid = min(128, N_NODES - nBase);

    cpa_tile(A, x + (size_t)nBase * 128, tid, valid);
    CP_COMMIT();
    load_B_tf32(B0, We1, tid, 512);
    load_B_tf32(B1, We1 + 128 * 128, tid, 512);
    CP_WAIT_ALL();
    __syncthreads();

    float acc1[2][4][4], acc2[2][4][4];
    zero_acc32(acc1); zero_acc32(acc2);
    mma_tile32_dual(A, B0, B1, acc1, acc2, lane, warpM, wc);

    // direct fp16-permuted stores: lane packs its 8 halves per (row, side)
    const int poff = wc * 32 + tig * 8;
#pragma unroll
    for (int side = 0; side < 2; ++side) {
        float (&acc)[2][4][4] = side ? acc2 : acc1;
#pragma unroll
        for (int mi = 0; mi < 2; ++mi)
#pragma unroll
            for (int half = 0; half < 2; ++half) {
                int m = warpM + mi * 16 + g + half * 8;
                int n = nBase + m;
                if (n < N_NODES) {
                    union { __half2 h[4]; uint4 u; } pk;
#pragma unroll
                    for (int ni = 0; ni < 4; ++ni)
                        pk.h[ni] = __floats2half2_rn(acc[mi][ni][half * 2],
                                                     acc[mi][ni][half * 2 + 1]);
                    *(uint4*)(g_P_h + (size_t)n * 256 + side * 128 + poff) = pk.u;
                }
            }
    }
}

// ---------------------------------------------------------------------------
// ekern v7: fp16 m16n8k16, dense B frags, fp16-permuted P gather (uint4/lane),
// two 8-warp groups, early S-prefetch, 2-pass output
// ---------------------------------------------------------------------------
__global__ __launch_bounds__(512, 1) void ekern(const float* __restrict__ attr,
                                                const float* __restrict__ We1,
                                                const float* __restrict__ be1,
                                                const float* __restrict__ We2,
                                                const float* __restrict__ be2,
                                                float* __restrict__ edge_out) {
    extern __shared__ float sm[];
    __half* Ah_base = (__half*)(sm + 2 * S_FLOATS);
    __half* B1h = Ah_base + 2 * AH_HALVES;
    __half* B2h = B1h + BH_HALVES;
    __shared__ int rows_s[2][2][64], cols_s[2][2][64];
    __shared__ float be1s[128], be2s[128];

    int tid = threadIdx.x, lane = tid & 31, wid = tid >> 5;
    int grp  = wid >> 3;
    int gtid = tid & 255;
    int gwid = wid & 7;
    int warpM = (gwid >> 2) << 5;
    int wc = gwid & 3;
    int g = lane >> 2, tig = lane & 3;
    const int cbase = wc * 32 + 2 * tig;
    const int poff = wc * 32 + tig * 8;     // fp16-permuted P offset for this lane
    float*  S  = sm + grp * S_FLOATS;
    __half* A  = Ah_base + grp * AH_HALVES;
    float*  A32 = (float*)A;

    load_B_h16(B1h, We1 + 2 * 128 * 128, tid, 512);  // W_e
    load_B_h16(B2h, We2, tid, 512);
    if (tid < 128) { be1s[tid] = be1[tid]; be2s[tid] = be2[tid]; }
    __syncthreads();

    const int NUM_T64 = N_EDGES / 64;     // 10000
    const int step = gridDim.x * 2;
    const int t0 = blockIdx.x * 2 + grp;

    // prologue
    {
        int eB = t0 << 6;
#pragma unroll
        for (int i = 0; i < 8; ++i) {
            int idx = gtid + i * 256;
            int r = idx >> 5, c4 = (idx & 31) << 2;
            cp_async16(smem_u32(S + r * LDA + c4), attr + (size_t)eB * 128 + r * 128 + c4, 16);
        }
        if (gtid < 16)
            cp_async16(smem_u32(&rows_s[grp][0][gtid * 4]), g_row + eB + gtid * 4, 16);
        else if (gtid < 32)
            cp_async16(smem_u32(&cols_s[grp][0][(gtid - 16) * 4]), g_col + eB + (gtid - 16) * 4, 16);
        CP_COMMIT();
    }

    int buf = 0;
    for (int t = t0; t < NUM_T64; t += step) {
        int eB = t << 6;
        CP_WAIT_ALL();
        GBAR(grp);   // S + indices visible

        // ---- convert S(fp32) -> A(fp16) ----
#pragma unroll
        for (int i = 0; i < 8; ++i) {
            int idx = gtid + i * 256;
            int r = idx >> 5, c4 = (idx & 31) << 2;
            float4 f = *(const float4*)(S + r * LDA + c4);
            union { __half2 h[2]; uint2 u; } cv;
            cv.h[0] = __floats2half2_rn(f.x, f.y);
            cv.h[1] = __floats2half2_rn(f.z, f.w);
            *(uint2*)(A + r * LDAH + c4) = cv.u;
        }
        GBAR(grp);   // A ready; S free

        // ---- early prefetch of next tile into S ----
        int tn = t + step;
        if (tn < NUM_T64) {
            int eN = tn << 6;
#pragma unroll
            for (int i = 0; i < 8; ++i) {
                int idx = gtid + i * 256;
                int r = idx >> 5, c4 = (idx & 31) << 2;
                cp_async16(smem_u32(S + r * LDA + c4), attr + (size_t)eN * 128 + r * 128 + c4, 16);
            }
            if (gtid < 16)
                cp_async16(smem_u32(&rows_s[grp][buf ^ 1][gtid * 4]), g_row + eN + gtid * 4, 16);
            else if (gtid < 32)
                cp_async16(smem_u32(&cols_s[grp][buf ^ 1][(gtid - 16) * 4]), g_col + eN + (gtid - 16) * 4, 16);
        }
        CP_COMMIT();

        // ---- P prefetch for mi=0 rows (one uint4 per row per matrix) ----
        int m0 = warpM + g, m1 = warpM + 8 + g;
        int r0 = rows_s[grp][buf][m0], c0i = cols_s[grp][buf][m0];
        int r1 = rows_s[grp][buf][m1], c1i = cols_s[grp][buf][m1];
        uint4 ups0[2], upd0[2];
        ups0[0] = *(const uint4*)(g_P_h + (size_t)r0 * 256 + poff);
        upd0[0] = *(const uint4*)(g_P_h + (size_t)c0i * 256 + 128 + poff);
        ups0[1] = *(const uint4*)(g_P_h + (size_t)r1 * 256 + poff);
        upd0[1] = *(const uint4*)(g_P_h + (size_t)c1i * 256 + 128 + poff);

        float acc1[2][4][4];
        zero_acc32(acc1);
        mma_h16(A, B1h, acc1, lane, warpM, wc);
        GBAR(grp);   // done reading A

        // ---- epilogue 1: h = relu(D1 + Psrc + Pdst + be1) -> A (fp16) ----
        {
            int m2 = warpM + 16 + g, m3 = warpM + 24 + g;
            int r2 = rows_s[grp][buf][m2], c2i = cols_s[grp][buf][m2];
            int r3 = rows_s[grp][buf][m3], c3i = cols_s[grp][buf][m3];
            uint4 ups1[2], upd1[2];
            ups1[0] = *(const uint4*)(g_P_h + (size_t)r2 * 256 + poff);
            upd1[0] = *(const uint4*)(g_P_h + (size_t)c2i * 256 + 128 + poff);
            ups1[1] = *(const uint4*)(g_P_h + (size_t)r3 * 256 + poff);
            upd1[1] = *(const uint4*)(g_P_h + (size_t)c3i * 256 + 128 + poff);

#pragma unroll
            for (int half = 0; half < 2; ++half) {
                int m = warpM + g + half * 8;
                const __half2* hs = (const __half2*)&ups0[half];
                const __half2* hd = (const __half2*)&upd0[half];
#pragma unroll
                for (int ni = 0; ni < 4; ++ni) {
                    int c = cbase + ni * 8;
                    float2 p = __half22float2(hs[ni]);
                    float2 q = __half22float2(hd[ni]);
                    float v0 = fmaxf(acc1[0][ni][half * 2]     + p.x + q.x + be1s[c],     0.f);
                    float v1 = fmaxf(acc1[0][ni][half * 2 + 1] + p.y + q.y + be1s[c + 1], 0.f);
                    *(__half2*)(A + m * LDAH + c) = __floats2half2_rn(v0, v1);
                }
            }
#pragma unroll
            for (int half = 0; half < 2; ++half) {
                int m = warpM + 16 + g + half * 8;
                const __half2* hs = (const __half2*)&ups1[half];
                const __half2* hd = (const __half2*)&upd1[half];
#pragma unroll
                for (int ni = 0; ni < 4; ++ni) {
                    int c = cbase + ni * 8;
                    float2 p = __half22float2(hs[ni]);
                    float2 q = __half22float2(hd[ni]);
                    float v0 = fmaxf(acc1[1][ni][half * 2]     + p.x + q.x + be1s[c],     0.f);
                    float v1 = fmaxf(acc1[1][ni][half * 2 + 1] + p.y + q.y + be1s[c + 1], 0.f);
                    *(__half2*)(A + m * LDAH + c) = __floats2half2_rn(v0, v1);
                }
            }
        }
        GBAR(grp);   // h visible

        float acc2[2][4][4];
        zero_acc32(acc2);
        mma_h16(A, B2h, acc2, lane, warpM, wc);
        GBAR(grp);   // done reading A(h)

        // ---- output: two 32-row passes staged through A32 ----
#pragma unroll
        for (int pass = 0; pass < 2; ++pass) {
            if ((warpM >> 5) == pass) {
#pragma unroll
                for (int mi = 0; mi < 2; ++mi)
#pragma unroll
                    for (int half = 0; half < 2; ++half) {
                        int m = mi * 16 + half * 8 + g;
#pragma unroll
                        for (int ni = 0; ni < 4; ++ni) {
                            int c = cbase + ni * 8;
                            *(float2*)(A32 + m * LDA + c) =
                                make_float2(acc2[mi][ni][half * 2]     + be2s[c],
                                            acc2[mi][ni][half * 2 + 1] + be2s[c + 1]);
                        }
                    }
            }
            GBAR(grp);   // staged
            {
                int rr = gtid >> 3;
                int grow = pass * 32 + rr;
                int rdst = rows_s[grp][buf][grow];
                float* eo = edge_out + (size_t)(eB + grow) * 128;
                float* ag = g_agg + (size_t)rdst * 128;
#pragma unroll
                for (int i = 0; i < 4; ++i) {
                    int c = ((gtid & 7) + i * 8) << 2;
                    float4 v = *(const float4*)(A32 + rr * LDA + c);
                    *(float4*)(eo + c) = v;
                    atomicAdd((float4*)(ag + c), v);
                }
            }
            GBAR(grp);   // readers done
        }
        buf ^= 1;
    }
}

// ---------------------------------------------------------------------------
// nkern (tf32, unchanged)
// ---------------------------------------------------------------------------
__global__ __launch_bounds__(512, 1) void nkern(const float* __restrict__ x,
                                                const float* __restrict__ Wn1,
                                                const float* __restrict__ bn1,
                                                const float* __restrict__ Wn2,
                                                const float* __restrict__ bn2,
                                                float* __restrict__ x_out) {
    extern __shared__ float sm[];
    float* A  = sm;
    float* B0 = sm + A_FLOATS;
    float* B1 = B0 + B_FLOATS;
    __shared__ float bn1s[128], bn2s[128], scale_s[128];

    int tid = threadIdx.x, lane = tid & 31, wid = tid >> 5;
    int warpM = (wid >> 2) << 5, wc = wid & 3;
    int g = lane >> 2, tig = lane & 3;
    int nBase = blockIdx.x * 128;
    int valid = min(128, N_NODES - nBase);

    cpa_tile(A, x + (size_t)nBase * 128, tid, valid);
    CP_COMMIT();
    load_B_tf32(B0, Wn1, tid, 512);
    load_B_tf32(B1, Wn1 + 128 * 128, tid, 512);
    if (tid < 128) {
        bn1s[tid] = bn1[tid];
        bn2s[tid] = bn2[tid];
        int n = nBase + tid;
        float c = (n < N_NODES) ? (float)g_cnt[n] : 1.f;
        scale_s[tid] = 1.f / fmaxf(c, 1.f);
    }
    CP_WAIT_ALL();
    __syncthreads();

    float acc[2][4][4];
    zero_acc32(acc);
    mma_tile32(A, B0, acc, lane, warpM, wc);
    __syncthreads();

    for (int i = tid; i < 4096; i += 512) {
        int r = i >> 5, c4 = (i & 31) << 2;
        int n = nBase + r;
        float4 v = make_float4(0.f, 0.f, 0.f, 0.f);
        if (n < N_NODES) {
            v = *(const float4*)(g_agg + (size_t)n * 128 + c4);
            float s = scale_s[r];
            v.x *= s; v.y *= s; v.z *= s; v.w *= s;
        }
        *(float4*)(A + r * LDA + c4) = v;
    }
    __syncthreads();
    mma_tile32(A, B1, acc, lane, warpM, wc);
    __syncthreads();

#pragma unroll
    for (int mi = 0; mi < 2; ++mi)
#pragma unroll
        for (int half = 0; half < 2; ++half) {
            int m = warpM + mi * 16 + g + half * 8;
#pragma unroll
            for (int ni = 0; ni < 4; ++ni) {
                int c = wc * 32 + ni * 8 + 2 * tig;
                float v0 = fmaxf(acc[mi][ni][half * 2]     + bn1s[c],     0.f);
                float v1 = fmaxf(acc[mi][ni][half * 2 + 1] + bn1s[c + 1], 0.f);
                *(float2*)(A + m * LDA + c) = make_float2(v0, v1);
            }
        }
    load_B_tf32(B0, Wn2, tid, 512);
    __syncthreads();

    float acc2[2][4][4];
    zero_acc32(acc2);
    mma_tile32(A, B0, acc2, lane, warpM, wc);
    __syncthreads();

#pragma unroll
    for (int mi = 0; mi < 2; ++mi)
#pragma unroll
        for (int half = 0; half < 2; ++half) {
            int m = warpM + mi * 16 + g + half * 8;
#pragma unroll
            for (int ni = 0; ni < 4; ++ni) {
                int c = wc * 32 + ni * 8 + 2 * tig;
                *(float2*)(A + m * LDA + c) =
                    make_float2(acc2[mi][ni][half * 2]     + bn2s[c],
                                acc2[mi][ni][half * 2 + 1] + bn2s[c + 1]);
            }
        }
    __syncthreads();
    {
        int row = tid >> 2;
        int n = nBase + row;
        if (n < N_NODES) {
#pragma unroll
            for (int i = 0; i < 8; ++i) {
                int c = ((tid & 3) + i * 4) << 2;
                *(float4*)(x_out + (size_t)n * 128 + c) = *(const float4*)(A + row * LDA + c);
            }
        }
    }
}

// ---------------------------------------------------------------------------
extern "C" void kernel_launch(void* const* d_in, const int* in_sizes, int n_in,
                              void* d_out, int out_size) {
    const float* x    = (const float*)d_in[0];
    const void*  eidx = d_in[1];
    const float* attr = (const float*)d_in[2];
    const float* We1  = (const float*)d_in[3];
    const float* be1  = (const float*)d_in[4];
    const float* We2  = (const float*)d_in[5];
    const float* be2  = (const float*)d_in[6];
    const float* Wn1  = (const float*)d_in[7];
    const float* bn1  = (const float*)d_in[8];
    const float* Wn2  = (const float*)d_in[9];
    const float* bn2  = (const float*)d_in[10];

    float* out      = (float*)d_out;
    float* x_out    = out;                          // [N, 128]
    float* edge_out = out + (size_t)N_NODES * 128;  // [E, 128]

    cudaFuncSetAttribute(pkern, cudaFuncAttributeMaxDynamicSharedMemorySize, SMEM_BYTES);
    cudaFuncSetAttribute(ekern, cudaFuncAttributeMaxDynamicSharedMemorySize, EK_SMEM);
    cudaFuncSetAttribute(nkern, cudaFuncAttributeMaxDynamicSharedMemorySize, SMEM_BYTES);

    zero_kern<<<640, 256>>>();
    conv_kern<<<640, 256>>>(eidx);
    pkern<<<(N_NODES + 127) / 128, 512, SMEM_BYTES>>>(x, We1);
    ekern<<<148, 512, EK_SMEM>>>(attr, We1, be1, We2, be2, edge_out);
    nkern<<<(N_NODES + 127) / 128, 512, SMEM_BYTES>>>(x, Wn1, bn1, Wn2, bn2, x_out);
}